// round 7
// baseline (speedup 1.0000x reference)
#include <cuda_runtime.h>
#include <math.h>

// Problem constants
#define B_ 64
#define S_ 197
#define E_ 768
#define H_ 12
#define HD_ 64
#define MROWS (B_ * S_)   // 12608

// Scratch: device globals (allocation-free rule)
__device__ float g_Q[(size_t)MROWS * E_];
__device__ float g_K[(size_t)MROWS * E_];
__device__ float g_V[(size_t)MROWS * E_];
__device__ float g_AO[(size_t)MROWS * E_];

// ---------------------------------------------------------------------------
// SGEMM: Y[M,768] = X[M,768] @ W[768,768]^T + bias
// 128x128x16 tiles, 256 threads, 8x8 per-thread register tile.
// in_sel:  0 -> Xext, 1 -> g_AO
// out_sel: 0 -> g_Q, 1 -> g_K, 2 -> g_V, 3 -> Yext
// ---------------------------------------------------------------------------
__global__ __launch_bounds__(256) void sgemm_bias(
    const float* __restrict__ Xext, const float* __restrict__ W,
    const float* __restrict__ bias, float* __restrict__ Yext,
    int M, int in_sel, int out_sel)
{
    constexpr int BM = 128, BN = 128, BK = 16, KD = 768;
    const float* X = (in_sel == 0) ? Xext : g_AO;
    float* Y = (out_sel == 0) ? g_Q
             : (out_sel == 1) ? g_K
             : (out_sel == 2) ? g_V
             : Yext;

    __shared__ float As[BK][BM + 4];
    __shared__ float Bs[BK][BN + 4];

    const int bm = blockIdx.y * BM;
    const int bn = blockIdx.x * BN;
    const int tid = threadIdx.x;
    const int tx = tid & 15;        // 0..15 -> N direction
    const int ty = tid >> 4;        // 0..15 -> M direction

    float acc[8][8];
#pragma unroll
    for (int i = 0; i < 8; i++)
#pragma unroll
        for (int j = 0; j < 8; j++) acc[i][j] = 0.f;

    const int lr = tid >> 2;          // 0..63 (row within half-tile)
    const int lc = (tid & 3) << 2;    // 0,4,8,12 (k-col group)

    for (int k0 = 0; k0 < KD; k0 += BK) {
        // Load A tile (X), transposed into As[k][m], with M guard
#pragma unroll
        for (int i = 0; i < 2; i++) {
            const int r = lr + i * 64;
            const int gm = bm + r;
            float4 v = make_float4(0.f, 0.f, 0.f, 0.f);
            if (gm < M)
                v = *reinterpret_cast<const float4*>(X + (size_t)gm * KD + k0 + lc);
            As[lc + 0][r] = v.x;
            As[lc + 1][r] = v.y;
            As[lc + 2][r] = v.z;
            As[lc + 3][r] = v.w;

            // Load B tile (W rows bn+n), transposed into Bs[k][n]; N=768 always full
            const int n = r;
            const float4 w4 =
                *reinterpret_cast<const float4*>(W + (size_t)(bn + n) * KD + k0 + lc);
            Bs[lc + 0][n] = w4.x;
            Bs[lc + 1][n] = w4.y;
            Bs[lc + 2][n] = w4.z;
            Bs[lc + 3][n] = w4.w;
        }
        __syncthreads();

#pragma unroll
        for (int k = 0; k < BK; k++) {
            float ra[8], rb[8];
#pragma unroll
            for (int i = 0; i < 8; i++) ra[i] = As[k][ty * 8 + i];
#pragma unroll
            for (int j = 0; j < 8; j++) rb[j] = Bs[k][tx * 8 + j];
#pragma unroll
            for (int i = 0; i < 8; i++)
#pragma unroll
                for (int j = 0; j < 8; j++)
                    acc[i][j] = fmaf(ra[i], rb[j], acc[i][j]);
        }
        __syncthreads();
    }

    // Epilogue: add bias, store with M guard
#pragma unroll
    for (int i = 0; i < 8; i++) {
        const int gm = bm + ty * 8 + i;
        if (gm < M) {
#pragma unroll
            for (int j = 0; j < 8; j++) {
                const int gn = bn + tx * 8 + j;
                Y[(size_t)gm * KD + gn] = acc[i][j] + bias[gn];
            }
        }
    }
}

// ---------------------------------------------------------------------------
// Fused attention: one CTA per (b,h).
//   energy = Qh @ Kh^T ; att = softmax(energy)/sqrt(E) ; out = att @ Vh
// Head layout follows the reference .view quirk:
//   Qh[s][d] = g_Q[b*S*E + h*S*HD + s*HD + d]
// K,V cached in smem (rows zero-padded to 224), Q processed 32 rows/tile.
// 256 threads = 8 warps; each warp owns 4 q-rows; softmax in registers+shfl.
// ---------------------------------------------------------------------------
#define SPAD 224          // padded sequence (multiple of 32)
#define KST  65           // K/V smem row stride (bank-conflict-free)
#define EST  224          // att-tile smem row stride

__global__ __launch_bounds__(256) void attn_fused(float* __restrict__ dummy)
{
    extern __shared__ float sm[];
    float* Ks = sm;                      // [224][65]
    float* Vs = Ks + SPAD * KST;         // [224][65]
    float* Qs = Vs + SPAD * KST;         // [32][64]
    float* Es = Qs + 32 * HD_;           // [32][224]

    const int bh = blockIdx.x;
    const int b = bh / H_;
    const int h = bh - b * H_;
    const size_t base = (size_t)b * S_ * E_ + (size_t)h * S_ * HD_;
    const float* Qp = g_Q + base;
    const float* Kp = g_K + base;
    const float* Vp = g_V + base;
    float* Op = g_AO + base;

    const int tid = threadIdx.x;
    const int warp = tid >> 5;
    const int lane = tid & 31;

    // Load K,V (zero-pad rows S_..SPAD-1)
    for (int idx = tid; idx < SPAD * 16; idx += 256) {
        const int j = idx >> 4;
        const int c = (idx & 15) << 2;
        float4 kv = make_float4(0.f, 0.f, 0.f, 0.f);
        float4 vv = make_float4(0.f, 0.f, 0.f, 0.f);
        if (j < S_) {
            kv = *reinterpret_cast<const float4*>(Kp + j * HD_ + c);
            vv = *reinterpret_cast<const float4*>(Vp + j * HD_ + c);
        }
        float* kd = Ks + j * KST + c;
        kd[0] = kv.x; kd[1] = kv.y; kd[2] = kv.z; kd[3] = kv.w;
        float* vd = Vs + j * KST + c;
        vd[0] = vv.x; vd[1] = vv.y; vd[2] = vv.z; vd[3] = vv.w;
    }

    const float inv_scale = 0.03608439182435162f;   // 1/sqrt(768)

    for (int q0 = 0; q0 < S_; q0 += 32) {
        // Load Q tile (zero-pad invalid rows)
        for (int idx = tid; idx < 32 * 16; idx += 256) {
            const int r = idx >> 4;
            const int c = (idx & 15) << 2;
            float4 qv = make_float4(0.f, 0.f, 0.f, 0.f);
            if (q0 + r < S_)
                qv = *reinterpret_cast<const float4*>(Qp + (q0 + r) * HD_ + c);
            float* qd = Qs + r * HD_ + c;
            qd[0] = qv.x; qd[1] = qv.y; qd[2] = qv.z; qd[3] = qv.w;
        }
        __syncthreads();

        // ---- Phase B: energy tile 32x197, warp owns rows warp*4..+3,
        //      lane owns columns lane, lane+32, ..., lane+192
        float e[4][7];
#pragma unroll
        for (int i = 0; i < 4; i++)
#pragma unroll
            for (int c = 0; c < 7; c++) e[i][c] = 0.f;

#pragma unroll 8
        for (int d = 0; d < HD_; d++) {
            float rq[4], rk[7];
#pragma unroll
            for (int i = 0; i < 4; i++)
                rq[i] = Qs[(warp * 4 + i) * HD_ + d];
#pragma unroll
            for (int c = 0; c < 7; c++)
                rk[c] = Ks[(lane + 32 * c) * KST + d];
#pragma unroll
            for (int i = 0; i < 4; i++)
#pragma unroll
                for (int c = 0; c < 7; c++)
                    e[i][c] = fmaf(rq[i], rk[c], e[i][c]);
        }

        // ---- Softmax per row (registers + warp shuffles), fold in 1/sqrt(E)
#pragma unroll
        for (int i = 0; i < 4; i++) {
#pragma unroll
            for (int c = 0; c < 7; c++)
                if (lane + 32 * c >= S_) e[i][c] = -INFINITY;

            float m = e[i][0];
#pragma unroll
            for (int c = 1; c < 7; c++) m = fmaxf(m, e[i][c]);
#pragma unroll
            for (int o = 16; o > 0; o >>= 1)
                m = fmaxf(m, __shfl_xor_sync(0xFFFFFFFFu, m, o));

            float s = 0.f;
#pragma unroll
            for (int c = 0; c < 7; c++) {
                const float ex = (lane + 32 * c < S_) ? __expf(e[i][c] - m) : 0.f;
                e[i][c] = ex;
                s += ex;
            }
#pragma unroll
            for (int o = 16; o > 0; o >>= 1)
                s += __shfl_xor_sync(0xFFFFFFFFu, s, o);

            const float inv = inv_scale / s;
#pragma unroll
            for (int c = 0; c < 7; c++)
                Es[(warp * 4 + i) * EST + lane + 32 * c] = e[i][c] * inv;
        }
        __syncthreads();

        // ---- Phase C: out tile 32x64 = att(32x197) @ V(197x64)
        float oa[4][2];
#pragma unroll
        for (int i = 0; i < 4; i++) { oa[i][0] = 0.f; oa[i][1] = 0.f; }

#pragma unroll 4
        for (int j = 0; j < S_; j++) {
            float ev[4];
#pragma unroll
            for (int i = 0; i < 4; i++)
                ev[i] = Es[(warp * 4 + i) * EST + j];
            const float v0 = Vs[j * KST + lane];
            const float v1 = Vs[j * KST + lane + 32];
#pragma unroll
            for (int i = 0; i < 4; i++) {
                oa[i][0] = fmaf(ev[i], v0, oa[i][0]);
                oa[i][1] = fmaf(ev[i], v1, oa[i][1]);
            }
        }

#pragma unroll
        for (int i = 0; i < 4; i++) {
            const int q = q0 + warp * 4 + i;
            if (q < S_) {
                Op[q * HD_ + lane]      = oa[i][0];
                Op[q * HD_ + lane + 32] = oa[i][1];
            }
        }
        __syncthreads();
    }
    if (dummy && tid == 12345) dummy[0] = 0.f;   // never true; keeps param used
}

// ---------------------------------------------------------------------------
// Launch
// ---------------------------------------------------------------------------
extern "C" void kernel_launch(void* const* d_in, const int* in_sizes, int n_in,
                              void* d_out, int out_size)
{
    const float* x  = (const float*)d_in[0];
    const float* Wq = (const float*)d_in[1];
    const float* bq = (const float*)d_in[2];
    const float* Wk = (const float*)d_in[3];
    const float* bk = (const float*)d_in[4];
    const float* Wv = (const float*)d_in[5];
    const float* bv = (const float*)d_in[6];
    const float* Wp = (const float*)d_in[7];
    const float* bp = (const float*)d_in[8];
    float* out = (float*)d_out;

    const int M = MROWS;  // 12608
    dim3 ggrid(E_ / 128, (M + 127) / 128);   // (6, 99)
    dim3 gblk(256);

    // QKV projections
    sgemm_bias<<<ggrid, gblk>>>(x, Wq, bq, nullptr, M, 0, 0);
    sgemm_bias<<<ggrid, gblk>>>(x, Wk, bk, nullptr, M, 0, 1);
    sgemm_bias<<<ggrid, gblk>>>(x, Wv, bv, nullptr, M, 0, 2);

    // Fused attention
    const int smem_bytes = (SPAD * KST * 2 + 32 * HD_ + 32 * EST) * (int)sizeof(float);
    cudaFuncSetAttribute(attn_fused, cudaFuncAttributeMaxDynamicSharedMemorySize,
                         smem_bytes);
    attn_fused<<<B_ * H_, 256, smem_bytes>>>(nullptr);

    // Output projection
    sgemm_bias<<<ggrid, gblk>>>(nullptr, Wp, bp, out, M, 1, 3);
}

// round 11
// speedup vs baseline: 1.8507x; 1.8507x over previous
#include <cuda_runtime.h>
#include <cuda_bf16.h>
#include <math.h>
#include <stdint.h>

// Problem constants
#define B_ 64
#define S_ 197
#define E_ 768
#define H_ 12
#define HD_ 64
#define MROWS (B_ * S_)   // 12608

// ---------------------------------------------------------------------------
// Scratch: device globals (allocation-free rule)
// ---------------------------------------------------------------------------
__device__ float g_Q [(size_t)MROWS * E_];
__device__ float g_K [(size_t)MROWS * E_];
__device__ float g_V [(size_t)MROWS * E_];
__device__ float g_AO[(size_t)MROWS * E_];

__device__ __align__(16) __nv_bfloat16 g_Xhi [(size_t)MROWS * E_];
__device__ __align__(16) __nv_bfloat16 g_Xlo [(size_t)MROWS * E_];
__device__ __align__(16) __nv_bfloat16 g_AOhi[(size_t)MROWS * E_];
__device__ __align__(16) __nv_bfloat16 g_AOlo[(size_t)MROWS * E_];
__device__ __align__(16) __nv_bfloat16 g_Whi [(size_t)4 * E_ * E_];
__device__ __align__(16) __nv_bfloat16 g_Wlo [(size_t)4 * E_ * E_];

// ---------------------------------------------------------------------------
// PTX helpers (arch-neutral: cp.async / ldmatrix / mma.sync — sm_80+)
// ---------------------------------------------------------------------------
__device__ __forceinline__ uint32_t smem_to_u32(const void* p) {
    uint32_t a;
    asm("{ .reg .u64 t; cvta.to.shared.u64 t, %1; cvt.u32.u64 %0, t; }"
        : "=r"(a) : "l"(p));
    return a;
}

__device__ __forceinline__ void cp16(uint32_t dst, const void* src, bool valid) {
    const int sz = valid ? 16 : 0;
    asm volatile("cp.async.cg.shared.global [%0], [%1], 16, %2;\n"
                 :: "r"(dst), "l"(src), "r"(sz));
}
__device__ __forceinline__ void cp_commit() {
    asm volatile("cp.async.commit_group;\n" ::: "memory");
}
template <int N>
__device__ __forceinline__ void cp_wait() {
    asm volatile("cp.async.wait_group %0;\n" :: "n"(N) : "memory");
}

__device__ __forceinline__ void ldm_x4(uint32_t addr, uint32_t& r0, uint32_t& r1,
                                       uint32_t& r2, uint32_t& r3) {
    asm volatile("ldmatrix.sync.aligned.m8n8.x4.shared.b16 {%0,%1,%2,%3}, [%4];"
                 : "=r"(r0), "=r"(r1), "=r"(r2), "=r"(r3) : "r"(addr));
}
__device__ __forceinline__ void ldm_x2(uint32_t addr, uint32_t& r0, uint32_t& r1) {
    asm volatile("ldmatrix.sync.aligned.m8n8.x2.shared.b16 {%0,%1}, [%2];"
                 : "=r"(r0), "=r"(r1) : "r"(addr));
}

__device__ __forceinline__ void mma16816(float* d, const uint32_t* a,
                                         const uint32_t* b) {
    asm volatile(
        "mma.sync.aligned.m16n8k16.row.col.f32.bf16.bf16.f32 "
        "{%0,%1,%2,%3}, {%4,%5,%6,%7}, {%8,%9}, {%0,%1,%2,%3};"
        : "+f"(d[0]), "+f"(d[1]), "+f"(d[2]), "+f"(d[3])
        : "r"(a[0]), "r"(a[1]), "r"(a[2]), "r"(a[3]), "r"(b[0]), "r"(b[1]));
}

// ---------------------------------------------------------------------------
// fp32 -> (bf16 hi, bf16 lo) split, vectorized float4
// dst_sel: 0 -> g_Xhi/g_Xlo   1 -> g_Whi/g_Wlo (+dst_off)   2 -> g_AOhi/g_AOlo
// ---------------------------------------------------------------------------
__global__ __launch_bounds__(256) void split_kernel(
    const float* __restrict__ src_ext, int n4, int dst_sel, int dst_off)
{
    __nv_bfloat16* hi = (dst_sel == 0) ? g_Xhi
                      : (dst_sel == 1) ? (g_Whi + dst_off) : g_AOhi;
    __nv_bfloat16* lo = (dst_sel == 0) ? g_Xlo
                      : (dst_sel == 1) ? (g_Wlo + dst_off) : g_AOlo;
    const float* src = (dst_sel == 2) ? g_AO : src_ext;

    const float4* s4 = reinterpret_cast<const float4*>(src);
    uint2* h4 = reinterpret_cast<uint2*>(hi);
    uint2* l4 = reinterpret_cast<uint2*>(lo);

    for (int i = blockIdx.x * 256 + threadIdx.x; i < n4; i += gridDim.x * 256) {
        const float4 v = s4[i];
        const __nv_bfloat16 h0 = __float2bfloat16(v.x);
        const __nv_bfloat16 h1 = __float2bfloat16(v.y);
        const __nv_bfloat16 h2 = __float2bfloat16(v.z);
        const __nv_bfloat16 h3 = __float2bfloat16(v.w);
        const __nv_bfloat16 l0 = __float2bfloat16(v.x - __bfloat162float(h0));
        const __nv_bfloat16 l1 = __float2bfloat16(v.y - __bfloat162float(h1));
        const __nv_bfloat16 l2 = __float2bfloat16(v.z - __bfloat162float(h2));
        const __nv_bfloat16 l3 = __float2bfloat16(v.w - __bfloat162float(h3));
        union { __nv_bfloat162 b2[2]; uint2 u; } H, L;
        H.b2[0] = __halves2bfloat162(h0, h1);
        H.b2[1] = __halves2bfloat162(h2, h3);
        L.b2[0] = __halves2bfloat162(l0, l1);
        L.b2[1] = __halves2bfloat162(l2, l3);
        h4[i] = H.u;
        l4[i] = L.u;
    }
}

// ---------------------------------------------------------------------------
// bf16x3 GEMM on mma.sync: Y[M,768] = X[M,768] @ W[768,768]^T + bias
// CTA 128x128, BK=32, 8 warps (2Mx4N), warp tile 64x32, cp.async dbl-buffer.
// ---------------------------------------------------------------------------
#define BKC        32
#define NTILES     (E_ / BKC)            // 24
#define LDS_ELEM   40                    // padded row stride (bf16 elems)
#define TILE_B     (128 * LDS_ELEM * 2)  // 10240 bytes per tile
#define OFF_AHI    0
#define OFF_ALO    (1 * TILE_B)
#define OFF_BHI    (2 * TILE_B)
#define OFF_BLO    (3 * TILE_B)
#define BUF_B      (4 * TILE_B)          // 40960
#define GSMEM_TOTAL (2 * BUF_B)          // 81920

__global__ __launch_bounds__(256, 2)
void tc_gemm(const float* __restrict__ bias, float* __restrict__ Yext,
             int in_sel, int w_off, int out_sel)
{
    extern __shared__ __align__(128) char smem[];
    const uint32_t sb = smem_to_u32(smem);
    const int tid = threadIdx.x;
    const int warp = tid >> 5;
    const int lane = tid & 31;
    const int wm = warp >> 2;      // 0..1
    const int wn = warp & 3;       // 0..3

    const __nv_bfloat16* __restrict__ Xhi = in_sel ? g_AOhi : g_Xhi;
    const __nv_bfloat16* __restrict__ Xlo = in_sel ? g_AOlo : g_Xlo;
    const __nv_bfloat16* __restrict__ Whi = g_Whi + w_off;
    const __nv_bfloat16* __restrict__ Wlo = g_Wlo + w_off;
    float* __restrict__ Y = (out_sel == 0) ? g_Q
                          : (out_sel == 1) ? g_K
                          : (out_sel == 2) ? g_V : Yext;

    const int bm = blockIdx.y * 128;
    const int bn = blockIdx.x * 128;

    float acc[4][4][4];
#pragma unroll
    for (int i = 0; i < 4; i++)
#pragma unroll
        for (int j = 0; j < 4; j++)
#pragma unroll
            for (int k = 0; k < 4; k++) acc[i][j][k] = 0.f;

    // ---- tile loader (cp.async, 16B chunks) --------------------------------
    auto load_tiles = [&](int it, int buf) {
        const int k0 = it * BKC;
        const uint32_t sbb = sb + buf * BUF_B;
#pragma unroll
        for (int i = 0; i < 2; i++) {
            const int idx = tid + i * 256;     // 0..511
            const int row = idx >> 2;          // 0..127
            const int c = idx & 3;             // 16B chunk
            const uint32_t soff = (uint32_t)(row * (LDS_ELEM * 2) + c * 16);

            const int gm = bm + row;
            const bool v = (gm < MROWS);
            const int gmc = v ? gm : 0;
            const size_t aoff = (size_t)gmc * E_ + k0 + c * 8;
            cp16(sbb + OFF_AHI + soff, Xhi + aoff, v);
            cp16(sbb + OFF_ALO + soff, Xlo + aoff, v);

            const size_t boff = (size_t)(bn + row) * E_ + k0 + c * 8;
            cp16(sbb + OFF_BHI + soff, Whi + boff, true);
            cp16(sbb + OFF_BLO + soff, Wlo + boff, true);
        }
        cp_commit();
    };

    load_tiles(0, 0);

    // per-warp ldmatrix address components (bytes)
    const int aRowB = (wm * 64 + (lane & 15)) * (LDS_ELEM * 2);
    const int aColB = (lane >> 4) * 16;
    const int bRowB = (wn * 32 + (lane & 7)) * (LDS_ELEM * 2);
    const int bColB = ((lane >> 3) & 1) * 16;

    for (int it = 0; it < NTILES; ++it) {
        if (it + 1 < NTILES) load_tiles(it + 1, (it + 1) & 1);

        if (it + 1 < NTILES) cp_wait<1>(); else cp_wait<0>();
        __syncthreads();

        const uint32_t sbb = sb + (uint32_t)(it & 1) * BUF_B;
#pragma unroll
        for (int ks = 0; ks < 2; ks++) {
            const int kB = ks * 32;   // 16 elems * 2B

            uint32_t Ahi[4][4], Bhi[4][2], Btmp[4][2];
#pragma unroll
            for (int mf = 0; mf < 4; mf++)
                ldm_x4(sbb + OFF_AHI + aRowB + mf * 16 * (LDS_ELEM * 2) + kB + aColB,
                       Ahi[mf][0], Ahi[mf][1], Ahi[mf][2], Ahi[mf][3]);
#pragma unroll
            for (int nf = 0; nf < 4; nf++)
                ldm_x2(sbb + OFF_BHI + bRowB + nf * 8 * (LDS_ELEM * 2) + kB + bColB,
                       Bhi[nf][0], Bhi[nf][1]);

            // hi * hi
#pragma unroll
            for (int mf = 0; mf < 4; mf++)
#pragma unroll
                for (int nf = 0; nf < 4; nf++)
                    mma16816(acc[mf][nf], Ahi[mf], Bhi[nf]);

            // hi * lo
#pragma unroll
            for (int nf = 0; nf < 4; nf++)
                ldm_x2(sbb + OFF_BLO + bRowB + nf * 8 * (LDS_ELEM * 2) + kB + bColB,
                       Btmp[nf][0], Btmp[nf][1]);
#pragma unroll
            for (int mf = 0; mf < 4; mf++)
#pragma unroll
                for (int nf = 0; nf < 4; nf++)
                    mma16816(acc[mf][nf], Ahi[mf], Btmp[nf]);

            // lo * hi  (reuse Ahi storage for Alo)
#pragma unroll
            for (int mf = 0; mf < 4; mf++)
                ldm_x4(sbb + OFF_ALO + aRowB + mf * 16 * (LDS_ELEM * 2) + kB + aColB,
                       Ahi[mf][0], Ahi[mf][1], Ahi[mf][2], Ahi[mf][3]);
#pragma unroll
            for (int mf = 0; mf < 4; mf++)
#pragma unroll
                for (int nf = 0; nf < 4; nf++)
                    mma16816(acc[mf][nf], Ahi[mf], Bhi[nf]);
        }
        __syncthreads();
    }

    // ---- epilogue: bias add + direct float2 stores -------------------------
#pragma unroll
    for (int mf = 0; mf < 4; mf++) {
        const int r0 = bm + wm * 64 + mf * 16 + (lane >> 2);
        const int r1 = r0 + 8;
#pragma unroll
        for (int nf = 0; nf < 4; nf++) {
            const int col = bn + wn * 32 + nf * 8 + 2 * (lane & 3);
            const float2 bv = *reinterpret_cast<const float2*>(bias + col);
            if (r0 < MROWS) {
                float2 o;
                o.x = acc[mf][nf][0] + bv.x;
                o.y = acc[mf][nf][1] + bv.y;
                *reinterpret_cast<float2*>(Y + (size_t)r0 * E_ + col) = o;
            }
            if (r1 < MROWS) {
                float2 o;
                o.x = acc[mf][nf][2] + bv.x;
                o.y = acc[mf][nf][3] + bv.y;
                *reinterpret_cast<float2*>(Y + (size_t)r1 * E_ + col) = o;
            }
        }
    }
}

// ---------------------------------------------------------------------------
// Fused attention (fp32): one CTA per (b,h), 512 threads, 64-row Q tiles.
// Head layout follows the reference .view quirk.
// ---------------------------------------------------------------------------
#define SPAD 224
#define KST  65
#define EST  224
#define QROWS 64

__global__ __launch_bounds__(512) void attn_fused()
{
    extern __shared__ float sm[];
    float* Ks = sm;                      // [224][65]
    float* Vs = Ks + SPAD * KST;         // [224][65]
    float* Qs = Vs + SPAD * KST;         // [64][64]
    float* Es = Qs + QROWS * HD_;        // [64][224]

    const int bh = blockIdx.x;
    const int b = bh / H_;
    const int h = bh - b * H_;
    const size_t base = (size_t)b * S_ * E_ + (size_t)h * S_ * HD_;
    const float* Qp = g_Q + base;
    const float* Kp = g_K + base;
    const float* Vp = g_V + base;
    float* Op = g_AO + base;

    const int tid = threadIdx.x;
    const int warp = tid >> 5;   // 0..15
    const int lane = tid & 31;

    // Load K,V (zero-pad rows S_..SPAD-1)
    for (int idx = tid; idx < SPAD * 16; idx += 512) {
        const int j = idx >> 4;
        const int c = (idx & 15) << 2;
        float4 kv = make_float4(0.f, 0.f, 0.f, 0.f);
        float4 vv = make_float4(0.f, 0.f, 0.f, 0.f);
        if (j < S_) {
            kv = *reinterpret_cast<const float4*>(Kp + j * HD_ + c);
            vv = *reinterpret_cast<const float4*>(Vp + j * HD_ + c);
        }
        float* kd = Ks + j * KST + c;
        kd[0] = kv.x; kd[1] = kv.y; kd[2] = kv.z; kd[3] = kv.w;
        float* vd = Vs + j * KST + c;
        vd[0] = vv.x; vd[1] = vv.y; vd[2] = vv.z; vd[3] = vv.w;
    }

    const float inv_scale = 0.03608439182435162f;   // 1/sqrt(768)

    for (int q0 = 0; q0 < S_; q0 += QROWS) {
        // Load Q tile (zero-pad invalid rows)
        for (int idx = tid; idx < QROWS * 16; idx += 512) {
            const int r = idx >> 4;
            const int c = (idx & 15) << 2;
            float4 qv = make_float4(0.f, 0.f, 0.f, 0.f);
            if (q0 + r < S_)
                qv = *reinterpret_cast<const float4*>(Qp + (q0 + r) * HD_ + c);
            float* qd = Qs + r * HD_ + c;
            qd[0] = qv.x; qd[1] = qv.y; qd[2] = qv.z; qd[3] = qv.w;
        }
        __syncthreads();

        // ---- energy tile 64x197; warp owns rows warp*4..+3
        float e[4][7];
#pragma unroll
        for (int i = 0; i < 4; i++)
#pragma unroll
            for (int c = 0; c < 7; c++) e[i][c] = 0.f;

#pragma unroll 8
        for (int d = 0; d < HD_; d++) {
            float rq[4], rk[7];
#pragma unroll
            for (int i = 0; i < 4; i++)
                rq[i] = Qs[(warp * 4 + i) * HD_ + d];
#pragma unroll
            for (int c = 0; c < 7; c++)
                rk[c] = Ks[(lane + 32 * c) * KST + d];
#pragma unroll
            for (int i = 0; i < 4; i++)
#pragma unroll
                for (int c = 0; c < 7; c++)
                    e[i][c] = fmaf(rq[i], rk[c], e[i][c]);
        }

        // ---- softmax per row (regs + shuffles), fold in 1/sqrt(E)
#pragma unroll
        for (int i = 0; i < 4; i++) {
#pragma unroll
            for (int c = 0; c < 7; c++)
                if (lane + 32 * c >= S_) e[i][c] = -INFINITY;

            float m = e[i][0];
#pragma unroll
            for (int c = 1; c < 7; c++) m = fmaxf(m, e[i][c]);
#pragma unroll
            for (int o = 16; o > 0; o >>= 1)
                m = fmaxf(m, __shfl_xor_sync(0xFFFFFFFFu, m, o));

            float s = 0.f;
#pragma unroll
            for (int c = 0; c < 7; c++) {
                const float ex = (lane + 32 * c < S_) ? __expf(e[i][c] - m) : 0.f;
                e[i][c] = ex;
                s += ex;
            }
#pragma unroll
            for (int o = 16; o > 0; o >>= 1)
                s += __shfl_xor_sync(0xFFFFFFFFu, s, o);

            const float inv = inv_scale / s;
#pragma unroll
            for (int c = 0; c < 7; c++)
                Es[(warp * 4 + i) * EST + lane + 32 * c] = e[i][c] * inv;
        }
        __syncthreads();

        // ---- out tile 64x64 = att(64x197) @ V(197x64)
        float oa[4][2];
#pragma unroll
        for (int i = 0; i < 4; i++) { oa[i][0] = 0.f; oa[i][1] = 0.f; }

#pragma unroll 4
        for (int j = 0; j < S_; j++) {
            float ev[4];
#pragma unroll
            for (int i = 0; i < 4; i++)
                ev[i] = Es[(warp * 4 + i) * EST + j];
            const float v0 = Vs[j * KST + lane];
            const float v1 = Vs[j * KST + lane + 32];
#pragma unroll
            for (int i = 0; i < 4; i++) {
                oa[i][0] = fmaf(ev[i], v0, oa[i][0]);
                oa[i][1] = fmaf(ev[i], v1, oa[i][1]);
            }
        }

#pragma unroll
        for (int i = 0; i < 4; i++) {
            const int q = q0 + warp * 4 + i;
            if (q < S_) {
                Op[q * HD_ + lane]      = oa[i][0];
                Op[q * HD_ + lane + 32] = oa[i][1];
            }
        }
        __syncthreads();
    }
}

// ---------------------------------------------------------------------------
// Launch
// ---------------------------------------------------------------------------
extern "C" void kernel_launch(void* const* d_in, const int* in_sizes, int n_in,
                              void* d_out, int out_size)
{
    const float* x  = (const float*)d_in[0];
    const float* Wq = (const float*)d_in[1];
    const float* bq = (const float*)d_in[2];
    const float* Wk = (const float*)d_in[3];
    const float* bk = (const float*)d_in[4];
    const float* Wv = (const float*)d_in[5];
    const float* bv = (const float*)d_in[6];
    const float* Wp = (const float*)d_in[7];
    const float* bp = (const float*)d_in[8];
    float* out = (float*)d_out;

    const int n4x = MROWS * E_ / 4;
    const int n4w = E_ * E_ / 4;
    const int WSZ = E_ * E_;

    // fp32 -> bf16 hi/lo splits
    split_kernel<<<1184, 256>>>(x,  n4x, 0, 0);
    split_kernel<<<592,  256>>>(Wq, n4w, 1, 0 * WSZ);
    split_kernel<<<592,  256>>>(Wk, n4w, 1, 1 * WSZ);
    split_kernel<<<592,  256>>>(Wv, n4w, 1, 2 * WSZ);
    split_kernel<<<592,  256>>>(Wp, n4w, 1, 3 * WSZ);

    // Tensor-core GEMMs: QKV projections
    cudaFuncSetAttribute(tc_gemm, cudaFuncAttributeMaxDynamicSharedMemorySize,
                         GSMEM_TOTAL);
    dim3 ggrid(E_ / 128, (MROWS + 127) / 128);   // (6, 99)
    tc_gemm<<<ggrid, 256, GSMEM_TOTAL>>>(bq, nullptr, 0, 0 * WSZ, 0);
    tc_gemm<<<ggrid, 256, GSMEM_TOTAL>>>(bk, nullptr, 0, 1 * WSZ, 1);
    tc_gemm<<<ggrid, 256, GSMEM_TOTAL>>>(bv, nullptr, 0, 2 * WSZ, 2);

    // Fused attention (fp32)
    const int smem_attn =
        (SPAD * KST * 2 + QROWS * HD_ + QROWS * EST) * (int)sizeof(float);
    cudaFuncSetAttribute(attn_fused, cudaFuncAttributeMaxDynamicSharedMemorySize,
                         smem_attn);
    attn_fused<<<B_ * H_, 512, smem_attn>>>();

    // Split attention output, then output projection
    split_kernel<<<1184, 256>>>(nullptr, n4x, 2, 0);
    tc_gemm<<<ggrid, 256, GSMEM_TOTAL>>>(bp, out, 1, 3 * WSZ, 3);
}